// round 7
// baseline (speedup 1.0000x reference)
#include <cuda_runtime.h>
#include <stdint.h>

#define BATCH 32
#define NBOX 24564
#define ROW 93
#define NUM_PRED 10
#define DB 64               // boxes per decode CTA
#define CCAP 1536           // smem candidate capacity in nms
#define TARGET 128          // desired compacted candidates per image

typedef unsigned long long u64;

// Scratch (static device globals; zero-initialized at load)
__device__ u64    g_key[BATCH * NBOX];   // dense: 0 = dead, else (score<<32)|(~idx)
__device__ int    g_cls[BATCH * NBOX];
__device__ float4 g_box[BATCH * NBOX];
__device__ int    g_hist[BATCH * 64];
__device__ u64    g_floor[BATCH];
__device__ int    g_ccount[BATCH];
__device__ u64    g_cand[BATCH * CCAP];

// Precise float exp: Cody-Waite + degree-6 FMA poly (~1 ulp), fast-math-proof.
__device__ __forceinline__ float exp_precise(float x) {
    x = fminf(fmaxf(x, -80.0f), 80.0f);
    float kf = rintf(x * 1.4426950408889634f);
    float r  = fmaf(-kf, 0.6931471824645996f, x);
    r        = fmaf(-kf, -1.904654323148236e-09f, r);
    float p  = 1.9875691500e-4f;
    p = fmaf(p, r, 1.3981999507e-3f);
    p = fmaf(p, r, 8.3334519073e-3f);
    p = fmaf(p, r, 4.1665795894e-2f);
    p = fmaf(p, r, 1.6666665459e-1f);
    p = fmaf(p, r, 5.0000000000e-1f);
    p = fmaf(p, r, 1.0f);
    p = fmaf(p, r, 1.0f);
    return p * __int_as_float(((int)kf + 127) << 23);
}

// Thread-per-box decode with smem staging + per-image score histogram.
__global__ __launch_bounds__(DB) void decode_kernel(const float* __restrict__ y) {
    __shared__ float s[DB * ROW];
    __shared__ int   h[64];
    const int b  = blockIdx.y;
    const int c0 = blockIdx.x * DB;
    const int nb = min(DB, NBOX - c0);
    const int nf4 = (nb * ROW) >> 2;
    const int t = threadIdx.x;

    h[t] = 0;                                  // DB == 64 bins
    const float4* src = (const float4*)(y + ((size_t)b * NBOX + c0) * ROW);
    float4* dst = (float4*)s;
    for (int i = t; i < nf4; i += DB) dst[i] = src[i];
    __syncthreads();

    if (t < nb) {
        const float* row = s + t * ROW;
        // argmax over 81 classes; '>' keeps first occurrence (jnp.argmax)
        float best = row[0]; int bi = 0;
        #pragma unroll
        for (int c = 1; c < 81; c++) {
            float v = row[c];
            if (v > best) { best = v; bi = c; }
        }
        const int box = c0 + t;
        const int p = b * NBOX + box;
        if (bi != 0 && best >= 0.5f) {
            float o0 = row[81], o1 = row[82], o2 = row[83], o3 = row[84];
            float cxp = row[85], cyp = row[86], wp = row[87], hp = row[88];
            float va = row[89], vb = row[90], vc = row[91], vd = row[92];
            float cx = o0 * va * wp + cxp;
            float cy = o1 * vb * hp + cyp;
            float w  = exp_precise(o2 * vc) * wp;
            float hh = exp_precise(o3 * vd) * hp;
            float4 bx;
            bx.x = (cx - 0.5f * w)  * 512.0f;
            bx.y = (cy - 0.5f * hh) * 512.0f;
            bx.z = (cx + 0.5f * w)  * 512.0f;
            bx.w = (cy + 0.5f * hh) * 512.0f;
            g_key[p] = ((u64)__float_as_uint(best) << 32) |
                       (u64)(0xFFFFFFFFu - (unsigned)box);
            g_cls[p] = bi;
            g_box[p] = bx;
            int bin = min(63, (int)((best - 0.5f) * 128.0f));  // exact binning
            atomicAdd(&h[bin], 1);
        } else {
            g_key[p] = 0ull;
        }
    }
    __syncthreads();
    int c = h[t];
    if (c) atomicAdd(&g_hist[b * 64 + t], c);
}

// One thread per image: find score floor admitting >= TARGET candidates
// (whole bins -> score-prefix set, ties included). Zero counters for replay.
__global__ __launch_bounds__(32) void thresh_kernel() {
    const int b = threadIdx.x;
    if (b >= BATCH) return;
    int* hh = g_hist + b * 64;
    int cum = 0, T = 0;
    for (int j = 63; j >= 0; j--) {
        cum += hh[j];
        if (cum >= TARGET) { T = j; break; }
    }
    float s = 0.5f + (float)T * 0.0078125f;        // exact bin edge
    g_floor[b]  = ((u64)__float_as_uint(s)) << 32;
    g_ccount[b] = 0;
    for (int j = 0; j < 64; j++) hh[j] = 0;        // ready for next replay
}

// Compact keys >= floor. grid (3, BATCH) x 256: covers 24576 slots.
__global__ __launch_bounds__(256) void compact_kernel() {
    const int b = blockIdx.y;
    const u64 fl = g_floor[b];
    const int base = b * NBOX;
    const int lane = threadIdx.x & 31;
    #pragma unroll 4
    for (int j = 0; j < 32; j++) {
        int idx = blockIdx.x * 8192 + threadIdx.x + j * 256;
        u64 k = (idx < NBOX) ? g_key[base + idx] : 0ull;
        bool pass = (k >= fl);                     // fl > 0, so pass implies k != 0
        unsigned m = __ballot_sync(0xffffffffu, pass);
        if (pass) {
            int leader = __ffs(m) - 1;
            int wb;
            if (lane == leader) wb = atomicAdd(&g_ccount[b], __popc(m));
            wb = __shfl_sync(m, wb, leader);
            int slot = wb + __popc(m & ((1u << lane) - 1u));
            if (slot < CCAP) g_cand[b * CCAP + slot] = k;
        }
    }
}

__device__ __forceinline__ bool iou_gt(const float4& a, const float4& q) {
    float iw = fminf(a.z, q.z) - fmaxf(a.x, q.x); iw = fmaxf(iw, 0.0f);
    float ih = fminf(a.w, q.w) - fmaxf(a.y, q.y); ih = fmaxf(ih, 0.0f);
    float inter  = iw * ih;
    float area_a = (a.z - a.x) * (a.w - a.y);
    float area_q = (q.z - q.x) * (q.w - q.y);
    return inter / (area_a + area_q - inter + 1e-12f) > 0.35f;
}

// One WARP per image. Fast path: greedy over compacted (score-prefix) set in
// smem. Exact continuation scans g_key below the floor if <10 picks found
// (also handles CCAP overflow). Picks held one-per-lane.
__global__ __launch_bounds__(32) void nms_kernel(float* __restrict__ out) {
    __shared__ u64    s_key[CCAP];
    __shared__ float4 s_box[CCAP];

    const int b    = blockIdx.x;
    const int lane = threadIdx.x;
    const int base = b * NBOX;
    const unsigned FULL = 0xffffffffu;

    for (int i = lane; i < NUM_PRED * 6; i += 32) out[b * NUM_PRED * 6 + i] = 0.0f;
    __syncwarp();

    const int M = g_ccount[b];
    u64 floork = g_floor[b];
    float4 pick = make_float4(0.f, 0.f, 0.f, 0.f);  // lane i holds pick i
    int np = 0;
    const bool fast = (M <= CCAP);

    if (fast) {
        for (int i = lane; i < M; i += 32) {
            u64 k = g_cand[b * CCAP + i];
            s_key[i] = k;
            unsigned orig = 0xFFFFFFFFu - (unsigned)k;
            s_box[i] = g_box[base + orig];
        }
        __syncwarp();

        while (np < NUM_PRED) {
            u64 lb = 0; int ls = -1;
            for (int i = lane; i < M; i += 32) {
                u64 k = s_key[i];
                if (k > lb) { lb = k; ls = i; }
            }
            u64 gb = lb;
            #pragma unroll
            for (int o = 16; o > 0; o >>= 1) {
                u64 t2 = __shfl_xor_sync(FULL, gb, o);
                gb = t2 > gb ? t2 : gb;
            }
            if (gb == 0ull) break;                 // compacted set exhausted
            unsigned own = __ballot_sync(FULL, lb == gb);
            int slot = __shfl_sync(FULL, ls, __ffs(own) - 1);
            float4 cand = s_box[slot];             // LDS broadcast
            if (lane == (__ffs(own) - 1)) s_key[slot] = 0ull;
            __syncwarp();
            bool hit = (lane < np) && iou_gt(cand, pick);
            if (__ballot_sync(FULL, hit) == 0u) {  // accepted
                if (lane == np) pick = cand;
                if (lane == 0) {
                    unsigned orig = 0xFFFFFFFFu - (unsigned)gb;
                    float* o = out + (b * NUM_PRED + np) * 6;
                    o[0] = (float)g_cls[base + orig];
                    o[1] = __uint_as_float((unsigned)(gb >> 32));
                    o[2] = cand.x; o[3] = cand.y; o[4] = cand.z; o[5] = cand.w;
                }
                np++;
            }
        }
    } else {
        floork = 0xFFFFFFFFFFFFFFFFull;            // overflow: scan everything
    }

    // Exact continuation below the floor (rare / never in practice)
    while (np < NUM_PRED) {
        u64 lb = 0;
        for (int i = lane; i < NBOX; i += 32) {
            u64 k = g_key[base + i];
            if (k < floork && k > lb) lb = k;
        }
        u64 gb = lb;
        #pragma unroll
        for (int o = 16; o > 0; o >>= 1) {
            u64 t2 = __shfl_xor_sync(FULL, gb, o);
            gb = t2 > gb ? t2 : gb;
        }
        if (gb == 0ull) break;
        floork = gb;
        unsigned orig = 0xFFFFFFFFu - (unsigned)gb;
        float4 cand = g_box[base + orig];
        bool hit = (lane < np) && iou_gt(cand, pick);
        if (__ballot_sync(FULL, hit) == 0u) {
            if (lane == np) pick = cand;
            if (lane == 0) {
                float* o = out + (b * NUM_PRED + np) * 6;
                o[0] = (float)g_cls[base + orig];
                o[1] = __uint_as_float((unsigned)(gb >> 32));
                o[2] = cand.x; o[3] = cand.y; o[4] = cand.z; o[5] = cand.w;
            }
            np++;
        }
    }
}

extern "C" void kernel_launch(void* const* d_in, const int* in_sizes, int n_in,
                              void* d_out, int out_size) {
    const float* y = (const float*)d_in[0];
    float* out = (float*)d_out;

    dim3 dgrid((NBOX + DB - 1) / DB, BATCH);
    decode_kernel<<<dgrid, DB>>>(y);

    thresh_kernel<<<1, 32>>>();

    dim3 cgrid(3, BATCH);
    compact_kernel<<<cgrid, 256>>>();

    nms_kernel<<<BATCH, 32>>>(out);
}

// round 8
// speedup vs baseline: 1.0197x; 1.0197x over previous
#include <cuda_runtime.h>
#include <stdint.h>

#define BATCH 32
#define NBOX 24564
#define ROW 93
#define NUM_PRED 10
#define DB 64               // boxes per decode CTA
#define CCAP 1536           // smem candidate capacity in fused post kernel
#define TARGET 128          // desired compacted candidates per image

typedef unsigned long long u64;

// Scratch (static device globals; zero-initialized at load)
__device__ u64    g_key[BATCH * NBOX];   // dense: 0 = dead, else (score<<32)|(~idx)
__device__ int    g_cls[BATCH * NBOX];
__device__ float4 g_box[BATCH * NBOX];
__device__ int    g_hist[BATCH * 64];

// Precise float exp: Cody-Waite + degree-6 FMA poly (~1 ulp), fast-math-proof.
__device__ __forceinline__ float exp_precise(float x) {
    x = fminf(fmaxf(x, -80.0f), 80.0f);
    float kf = rintf(x * 1.4426950408889634f);
    float r  = fmaf(-kf, 0.6931471824645996f, x);
    r        = fmaf(-kf, -1.904654323148236e-09f, r);
    float p  = 1.9875691500e-4f;
    p = fmaf(p, r, 1.3981999507e-3f);
    p = fmaf(p, r, 8.3334519073e-3f);
    p = fmaf(p, r, 4.1665795894e-2f);
    p = fmaf(p, r, 1.6666665459e-1f);
    p = fmaf(p, r, 5.0000000000e-1f);
    p = fmaf(p, r, 1.0f);
    p = fmaf(p, r, 1.0f);
    return p * __int_as_float(((int)kf + 127) << 23);
}

__device__ __forceinline__ void cp16(uint32_t dst_smem, const void* src) {
    asm volatile("cp.async.cg.shared.global [%0], [%1], 16;"
                 :: "r"(dst_smem), "l"(src));
}

// Thread-per-box decode: cp.async staging into smem, per-thread argmax,
// per-image score histogram (64 bins over [0.5,1], exact fp32 edges).
__global__ __launch_bounds__(DB) void decode_kernel(const float* __restrict__ y) {
    __shared__ float s[DB * ROW];
    __shared__ int   h[64];
    const int b  = blockIdx.y;
    const int c0 = blockIdx.x * DB;
    const int nb = min(DB, NBOX - c0);
    const int nf4 = (nb * ROW) >> 2;
    const int t = threadIdx.x;

    h[t] = 0;
    {
        const float4* src = (const float4*)(y + ((size_t)b * NBOX + c0) * ROW);
        uint32_t sbase;
        asm("{ .reg .u64 tmp; cvta.to.shared.u64 tmp, %1; cvt.u32.u64 %0, tmp; }"
            : "=r"(sbase) : "l"(s));
        for (int i = t; i < nf4; i += DB) cp16(sbase + i * 16, src + i);
        asm volatile("cp.async.commit_group;" ::: "memory");
        asm volatile("cp.async.wait_group 0;" ::: "memory");
    }
    __syncthreads();

    if (t < nb) {
        const float* row = s + t * ROW;
        // argmax over 81 classes; '>' keeps first occurrence (jnp.argmax)
        float best = row[0]; int bi = 0;
        #pragma unroll
        for (int c = 1; c < 81; c++) {
            float v = row[c];
            if (v > best) { best = v; bi = c; }
        }
        const int box = c0 + t;
        const int p = b * NBOX + box;
        if (bi != 0 && best >= 0.5f) {
            float o0 = row[81], o1 = row[82], o2 = row[83], o3 = row[84];
            float cxp = row[85], cyp = row[86], wp = row[87], hp = row[88];
            float va = row[89], vb = row[90], vc = row[91], vd = row[92];
            float cx = o0 * va * wp + cxp;
            float cy = o1 * vb * hp + cyp;
            float w  = exp_precise(o2 * vc) * wp;
            float hh = exp_precise(o3 * vd) * hp;
            float4 bx;
            bx.x = (cx - 0.5f * w)  * 512.0f;
            bx.y = (cy - 0.5f * hh) * 512.0f;
            bx.z = (cx + 0.5f * w)  * 512.0f;
            bx.w = (cy + 0.5f * hh) * 512.0f;
            g_key[p] = ((u64)__float_as_uint(best) << 32) |
                       (u64)(0xFFFFFFFFu - (unsigned)box);
            g_cls[p] = bi;
            g_box[p] = bx;
            int bin = min(63, (int)((best - 0.5f) * 128.0f));
            atomicAdd(&h[bin], 1);
        } else {
            g_key[p] = 0ull;
        }
    }
    __syncthreads();
    int c = h[t];
    if (c) atomicAdd(&g_hist[b * 64 + t], c);
}

__device__ __forceinline__ bool iou_gt(const float4& a, const float4& q) {
    float iw = fminf(a.z, q.z) - fmaxf(a.x, q.x); iw = fmaxf(iw, 0.0f);
    float ih = fminf(a.w, q.w) - fmaxf(a.y, q.y); ih = fmaxf(ih, 0.0f);
    float inter  = iw * ih;
    float area_a = (a.z - a.x) * (a.w - a.y);
    float area_q = (q.z - q.x) * (q.w - q.y);
    return inter / (area_a + area_q - inter + 1e-12f) > 0.35f;
}

// Fused post-processing: one 256-thread CTA per image.
// Phase 1 (warp0+warp1): read+zero hist, compute score floor (>= TARGET cands).
// Phase 2 (all warps):   compact keys >= floor into smem (+ their boxes).
// Phase 3 (warp 0):      greedy NMS over the score-prefix set in smem;
//                        exact global continuation below floor if needed.
__global__ __launch_bounds__(256) void post_kernel(float* __restrict__ out) {
    __shared__ u64    s_key[CCAP];
    __shared__ float4 s_box[CCAP];
    __shared__ int    s_h[64];
    __shared__ int    s_cnt;
    __shared__ u64    s_floor;

    const int b    = blockIdx.x;
    const int tid  = threadIdx.x;
    const int lane = tid & 31;
    const int base = b * NBOX;
    const unsigned FULL = 0xffffffffu;

    if (tid < NUM_PRED * 6) out[b * NUM_PRED * 6 + tid] = 0.0f;
    if (tid < 64) {                      // read + zero hist for next replay
        s_h[tid] = g_hist[b * 64 + tid];
        g_hist[b * 64 + tid] = 0;
    }
    if (tid == 0) s_cnt = 0;
    __syncthreads();

    if (tid == 0) {
        int cum = 0, T = 0;
        for (int j = 63; j >= 0; j--) {
            cum += s_h[j];
            if (cum >= TARGET) { T = j; break; }
        }
        float sc = 0.5f + (float)T * 0.0078125f;   // exact bin edge
        s_floor = ((u64)__float_as_uint(sc)) << 32;
    }
    __syncthreads();
    const u64 floork = s_floor;

    // ---- Phase 2: compact (96 strided passes of 256 threads) ----
    #pragma unroll 4
    for (int j = 0; j < 96; j++) {
        int idx = tid + j * 256;
        u64 k = (idx < NBOX) ? g_key[base + idx] : 0ull;
        bool pass = (k >= floork);       // floork > 0 => pass implies alive
        unsigned m = __ballot_sync(FULL, pass);
        if (pass) {
            int leader = __ffs(m) - 1;
            int wb;
            if (lane == leader) wb = atomicAdd(&s_cnt, __popc(m));
            wb = __shfl_sync(m, wb, leader);
            int slot = wb + __popc(m & ((1u << lane) - 1u));
            if (slot < CCAP) {
                s_key[slot] = k;
                s_box[slot] = g_box[base + idx];   // idx == orig box
            }
        }
    }
    __syncthreads();

    // ---- Phase 3: warp 0 greedy NMS ----
    if (tid >= 32) return;
    const int M = s_cnt;
    float4 pick = make_float4(0.f, 0.f, 0.f, 0.f);  // lane i holds pick i
    int np = 0;
    u64 cont_floor = floork;

    if (M <= CCAP) {
        while (np < NUM_PRED) {
            u64 lb = 0; int ls = -1;
            for (int i = lane; i < M; i += 32) {
                u64 k = s_key[i];
                if (k > lb) { lb = k; ls = i; }
            }
            u64 gb = lb;
            #pragma unroll
            for (int o = 16; o > 0; o >>= 1) {
                u64 t2 = __shfl_xor_sync(FULL, gb, o);
                gb = t2 > gb ? t2 : gb;
            }
            if (gb == 0ull) break;                 // prefix set exhausted
            unsigned own = __ballot_sync(FULL, lb == gb);
            int slot = __shfl_sync(FULL, ls, __ffs(own) - 1);
            float4 cand = s_box[slot];
            if (lane == (__ffs(own) - 1)) s_key[slot] = 0ull;
            __syncwarp();
            bool hit = (lane < np) && iou_gt(cand, pick);
            if (__ballot_sync(FULL, hit) == 0u) {
                if (lane == np) pick = cand;
                if (lane == 0) {
                    unsigned orig = 0xFFFFFFFFu - (unsigned)gb;
                    float* o = out + (b * NUM_PRED + np) * 6;
                    o[0] = (float)g_cls[base + orig];
                    o[1] = __uint_as_float((unsigned)(gb >> 32));
                    o[2] = cand.x; o[3] = cand.y; o[4] = cand.z; o[5] = cand.w;
                }
                np++;
            }
        }
    } else {
        cont_floor = 0xFFFFFFFFFFFFFFFFull;        // overflow: scan everything
        np = 0;
    }

    // Exact continuation below the floor (rare / never in practice)
    while (np < NUM_PRED) {
        u64 lb = 0;
        for (int i = lane; i < NBOX; i += 32) {
            u64 k = g_key[base + i];
            if (k < cont_floor && k > lb) lb = k;
        }
        u64 gb = lb;
        #pragma unroll
        for (int o = 16; o > 0; o >>= 1) {
            u64 t2 = __shfl_xor_sync(FULL, gb, o);
            gb = t2 > gb ? t2 : gb;
        }
        if (gb == 0ull) break;
        cont_floor = gb;
        unsigned orig = 0xFFFFFFFFu - (unsigned)gb;
        float4 cand = g_box[base + orig];
        bool hit = (lane < np) && iou_gt(cand, pick);
        if (__ballot_sync(FULL, hit) == 0u) {
            if (lane == np) pick = cand;
            if (lane == 0) {
                float* o = out + (b * NUM_PRED + np) * 6;
                o[0] = (float)g_cls[base + orig];
                o[1] = __uint_as_float((unsigned)(gb >> 32));
                o[2] = cand.x; o[3] = cand.y; o[4] = cand.z; o[5] = cand.w;
            }
            np++;
        }
    }
}

extern "C" void kernel_launch(void* const* d_in, const int* in_sizes, int n_in,
                              void* d_out, int out_size) {
    const float* y = (const float*)d_in[0];
    float* out = (float*)d_out;

    dim3 dgrid((NBOX + DB - 1) / DB, BATCH);
    decode_kernel<<<dgrid, DB>>>(y);

    post_kernel<<<BATCH, 256>>>(out);
}